// round 1
// baseline (speedup 1.0000x reference)
#include <cuda_runtime.h>

// ---------------------------------------------------------------------------
// PCT position-embedding + 4 stacked offset-attention SA layers (eval mode).
// B=8, C=256, D=C/4=64, N=2048. All fp32.
// ---------------------------------------------------------------------------

#define B_   8
#define C_   256
#define D_   64
#define N_   2048
#define EPSB 1e-5f

// Static device scratch (no runtime allocation allowed).
__device__ float g_pos[B_ * C_ * N_];
__device__ float g_h0 [B_ * C_ * N_];
__device__ float g_h1 [B_ * C_ * N_];
__device__ float g_hp [B_ * C_ * N_];
__device__ float g_q  [B_ * D_ * N_];
__device__ float g_val[B_ * C_ * N_];
__device__ float g_xr [B_ * C_ * N_];
__device__ float g_att[(long long)B_ * N_ * N_];   // 134 MB
__device__ float g_cs [B_ * N_];

// ---------------------------------------------------------------------------
// Generic tiled SGEMM: Cmat[M,N_] = A[M,K] @ Bmat[K,N_]  (row-major, N_=2048)
// Epilogue variants selected by template.
// ---------------------------------------------------------------------------
enum { EPI_BN_RELU = 0, EPI_BIAS = 1, EPI_COLSCALE = 2, EPI_T_UPDATE = 3 };

template <int EPI, bool BSUB>
__global__ void __launch_bounds__(256, 2)
gemm_kernel(const float* __restrict__ A, long aBatch, int M, int K,
            const float* __restrict__ Bmat, long bBatch,
            const float* __restrict__ Bsub,
            float* __restrict__ Cmat, long cBatch,
            const float* __restrict__ bias,
            const float* __restrict__ bng, const float* __restrict__ bnb,
            const float* __restrict__ bnm, const float* __restrict__ bnv,
            const float* __restrict__ colsum,
            const float* __restrict__ hres,
            float* __restrict__ out2, long out2Batch)
{
    __shared__ float AsT[16][132];   // transposed A tile [k][m], padded
    __shared__ float Bt [16][128];   // B tile [k][n]

    const int b  = blockIdx.z;
    const float* Ab = A    + (long)b * aBatch;
    const float* Bb = Bmat + (long)b * bBatch;
    const float* Sb = BSUB ? (Bsub + (long)b * bBatch) : nullptr;

    const int m0 = blockIdx.y * 128;
    const int n0 = blockIdx.x * 128;
    const int t  = threadIdx.x;
    const int tx = t & 15;
    const int ty = t >> 4;

    float acc[8][8];
#pragma unroll
    for (int i = 0; i < 8; i++)
#pragma unroll
        for (int j = 0; j < 8; j++) acc[i][j] = 0.f;

    const int aRow = t >> 2;          // 0..63 (+64 second half)
    const int aCol = (t & 3) << 2;    // 0,4,8,12
    const int bRow = t >> 5;          // 0..7 (+8 second half)
    const int bCol = (t & 31) << 2;   // 0..124

    for (int k0 = 0; k0 < K; k0 += 16) {
        // ---- load A tile (transposed into smem) ----
#pragma unroll
        for (int h = 0; h < 2; h++) {
            int row = aRow + h * 64;
            int gm  = m0 + row;
            float4 v = make_float4(0.f, 0.f, 0.f, 0.f);
            if (gm < M)
                v = *reinterpret_cast<const float4*>(Ab + (long)gm * K + k0 + aCol);
            AsT[aCol + 0][row] = v.x;
            AsT[aCol + 1][row] = v.y;
            AsT[aCol + 2][row] = v.z;
            AsT[aCol + 3][row] = v.w;
        }
        // ---- load B tile ----
#pragma unroll
        for (int h = 0; h < 2; h++) {
            int kr = bRow + h * 8;
            long off = (long)(k0 + kr) * N_ + n0 + bCol;
            float4 v = *reinterpret_cast<const float4*>(Bb + off);
            if (BSUB) {
                float4 s = *reinterpret_cast<const float4*>(Sb + off);
                v.x -= s.x; v.y -= s.y; v.z -= s.z; v.w -= s.w;
            }
            *reinterpret_cast<float4*>(&Bt[kr][bCol]) = v;
        }
        __syncthreads();

#pragma unroll
        for (int k = 0; k < 16; k++) {
            float ar[8], br[8];
            float4 a0 = *reinterpret_cast<const float4*>(&AsT[k][ty * 8 + 0]);
            float4 a1 = *reinterpret_cast<const float4*>(&AsT[k][ty * 8 + 4]);
            float4 b0 = *reinterpret_cast<const float4*>(&Bt [k][tx * 8 + 0]);
            float4 b1 = *reinterpret_cast<const float4*>(&Bt [k][tx * 8 + 4]);
            ar[0]=a0.x; ar[1]=a0.y; ar[2]=a0.z; ar[3]=a0.w;
            ar[4]=a1.x; ar[5]=a1.y; ar[6]=a1.z; ar[7]=a1.w;
            br[0]=b0.x; br[1]=b0.y; br[2]=b0.z; br[3]=b0.w;
            br[4]=b1.x; br[5]=b1.y; br[6]=b1.z; br[7]=b1.w;
#pragma unroll
            for (int i = 0; i < 8; i++)
#pragma unroll
                for (int j = 0; j < 8; j++)
                    acc[i][j] = fmaf(ar[i], br[j], acc[i][j]);
        }
        __syncthreads();
    }

    // ---- epilogue ----
    float* Cb = Cmat + (long)b * cBatch;
#pragma unroll
    for (int i = 0; i < 8; i++) {
        int gm = m0 + ty * 8 + i;
        if (gm < M) {
            float s = 1.f, sh = 0.f, bs = 0.f;
            if (EPI == EPI_BN_RELU || EPI == EPI_T_UPDATE) {
                float inv = rsqrtf(bnv[gm] + EPSB);
                s  = bng[gm] * inv;
                sh = bnb[gm] - bnm[gm] * s;
            }
            if (EPI == EPI_T_UPDATE) bs = bias[gm];
            if (EPI == EPI_BIAS && bias != nullptr) bs = bias[gm];

            float vv[8];
#pragma unroll
            for (int j = 0; j < 8; j++) {
                int gn = n0 + tx * 8 + j;
                float v = acc[i][j];
                if (EPI == EPI_BN_RELU) {
                    v = fmaxf(fmaf(v, s, sh), 0.f);
                } else if (EPI == EPI_BIAS) {
                    v += bs;
                } else if (EPI == EPI_COLSCALE) {
                    v = v / (1e-9f + colsum[b * N_ + gn]);
                } else { // EPI_T_UPDATE
                    v = fmaxf(fmaf(v + bs, s, sh), 0.f);
                }
                vv[j] = v;
            }
            long base = (long)gm * N_ + n0 + tx * 8;
            if (EPI == EPI_T_UPDATE) {
                const float* hr = hres + (long)b * ((long)C_ * N_);
                float4 h0 = *reinterpret_cast<const float4*>(hr + base + 0);
                float4 h1 = *reinterpret_cast<const float4*>(hr + base + 4);
                vv[0]+=h0.x; vv[1]+=h0.y; vv[2]+=h0.z; vv[3]+=h0.w;
                vv[4]+=h1.x; vv[5]+=h1.y; vv[6]+=h1.z; vv[7]+=h1.w;
                float* o2 = out2 + (long)b * out2Batch;
                *reinterpret_cast<float4*>(o2 + base + 0) = make_float4(vv[0],vv[1],vv[2],vv[3]);
                *reinterpret_cast<float4*>(o2 + base + 4) = make_float4(vv[4],vv[5],vv[6],vv[7]);
            }
            *reinterpret_cast<float4*>(Cb + base + 0) = make_float4(vv[0],vv[1],vv[2],vv[3]);
            *reinterpret_cast<float4*>(Cb + base + 4) = make_float4(vv[4],vv[5],vv[6],vv[7]);
        }
    }
}

// ---------------------------------------------------------------------------
// energy[b][n][m] = sum_d Q[b][d][n] * Q[b][d][m]   (Q: [B][D][N], K-major)
// ---------------------------------------------------------------------------
__global__ void __launch_bounds__(256, 2)
energy_kernel(const float* __restrict__ Q, float* __restrict__ E)
{
    __shared__ float Qa[16][128];
    __shared__ float Qc[16][128];

    const int b = blockIdx.z;
    const float* Qb = Q + (long)b * D_ * N_;
    float* Eb = E + (long)b * (long)N_ * N_;

    const int n0 = blockIdx.y * 128;
    const int m0 = blockIdx.x * 128;
    const int t  = threadIdx.x;
    const int tx = t & 15;
    const int ty = t >> 4;

    float acc[8][8];
#pragma unroll
    for (int i = 0; i < 8; i++)
#pragma unroll
        for (int j = 0; j < 8; j++) acc[i][j] = 0.f;

    const int bRow = t >> 5;
    const int bCol = (t & 31) << 2;

    for (int k0 = 0; k0 < D_; k0 += 16) {
#pragma unroll
        for (int h = 0; h < 2; h++) {
            int kr = bRow + h * 8;
            *reinterpret_cast<float4*>(&Qa[kr][bCol]) =
                *reinterpret_cast<const float4*>(Qb + (long)(k0 + kr) * N_ + n0 + bCol);
            *reinterpret_cast<float4*>(&Qc[kr][bCol]) =
                *reinterpret_cast<const float4*>(Qb + (long)(k0 + kr) * N_ + m0 + bCol);
        }
        __syncthreads();
#pragma unroll
        for (int k = 0; k < 16; k++) {
            float ar[8], br[8];
            float4 a0 = *reinterpret_cast<const float4*>(&Qa[k][ty * 8 + 0]);
            float4 a1 = *reinterpret_cast<const float4*>(&Qa[k][ty * 8 + 4]);
            float4 b0 = *reinterpret_cast<const float4*>(&Qc[k][tx * 8 + 0]);
            float4 b1 = *reinterpret_cast<const float4*>(&Qc[k][tx * 8 + 4]);
            ar[0]=a0.x; ar[1]=a0.y; ar[2]=a0.z; ar[3]=a0.w;
            ar[4]=a1.x; ar[5]=a1.y; ar[6]=a1.z; ar[7]=a1.w;
            br[0]=b0.x; br[1]=b0.y; br[2]=b0.z; br[3]=b0.w;
            br[4]=b1.x; br[5]=b1.y; br[6]=b1.z; br[7]=b1.w;
#pragma unroll
            for (int i = 0; i < 8; i++)
#pragma unroll
                for (int j = 0; j < 8; j++)
                    acc[i][j] = fmaf(ar[i], br[j], acc[i][j]);
        }
        __syncthreads();
    }

#pragma unroll
    for (int i = 0; i < 8; i++) {
        long base = (long)(n0 + ty * 8 + i) * N_ + m0 + tx * 8;
        *reinterpret_cast<float4*>(Eb + base + 0) = make_float4(acc[i][0],acc[i][1],acc[i][2],acc[i][3]);
        *reinterpret_cast<float4*>(Eb + base + 4) = make_float4(acc[i][4],acc[i][5],acc[i][6],acc[i][7]);
    }
}

// ---------------------------------------------------------------------------
// Row softmax over last dim (in place).  One block per (b, n) row.
// ---------------------------------------------------------------------------
__global__ void __launch_bounds__(256)
softmax_kernel(float* __restrict__ E)
{
    long row = blockIdx.x;
    float* r = E + row * (long)N_;
    const int t = threadIdx.x;

    float v[8];
    float mx = -3.4e38f;
#pragma unroll
    for (int i = 0; i < 8; i++) { v[i] = r[t + 256 * i]; mx = fmaxf(mx, v[i]); }

    __shared__ float red[8];
#pragma unroll
    for (int o = 16; o > 0; o >>= 1) mx = fmaxf(mx, __shfl_xor_sync(0xffffffffu, mx, o));
    if ((t & 31) == 0) red[t >> 5] = mx;
    __syncthreads();
    float bm = red[0];
#pragma unroll
    for (int w = 1; w < 8; w++) bm = fmaxf(bm, red[w]);
    __syncthreads();

    float sum = 0.f;
#pragma unroll
    for (int i = 0; i < 8; i++) { v[i] = expf(v[i] - bm); sum += v[i]; }
#pragma unroll
    for (int o = 16; o > 0; o >>= 1) sum += __shfl_xor_sync(0xffffffffu, sum, o);
    if ((t & 31) == 0) red[t >> 5] = sum;
    __syncthreads();
    float tot = 0.f;
#pragma unroll
    for (int w = 0; w < 8; w++) tot += red[w];

    float inv = 1.f / tot;
#pragma unroll
    for (int i = 0; i < 8; i++) r[t + 256 * i] = v[i] * inv;
}

// ---------------------------------------------------------------------------
// colsum[b][m] = sum_n att[b][n][m]   (atomic partial sums over 128-row chunks)
// ---------------------------------------------------------------------------
__global__ void __launch_bounds__(256)
colsum_kernel(const float* __restrict__ E, float* __restrict__ cs)
{
    const int b   = blockIdx.z;
    const int col = blockIdx.x * 256 + threadIdx.x;
    const int r0  = blockIdx.y * 128;
    const float* Eb = E + (long)b * (long)N_ * N_;
    float s = 0.f;
#pragma unroll 4
    for (int r = 0; r < 128; r++) s += Eb[(long)(r0 + r) * N_ + col];
    atomicAdd(&cs[b * N_ + col], s);
}

__global__ void zero_kernel(float* __restrict__ p, int n)
{
    int i = blockIdx.x * 256 + threadIdx.x;
    if (i < n) p[i] = 0.f;
}

// pos[b][c][n] = sum_i convpos_w[c][i] * xyz[b][n][i]
__global__ void pos_kernel(const float* __restrict__ w, const float* __restrict__ xyz)
{
    long idx = (long)blockIdx.x * 256 + threadIdx.x;
    if (idx >= (long)B_ * C_ * N_) return;
    int n = (int)(idx % N_);
    int c = (int)((idx / N_) % C_);
    int b = (int)(idx / ((long)C_ * N_));
    const float* p = xyz + ((long)b * N_ + n) * 3;
    g_pos[idx] = w[c * 3 + 0] * p[0] + w[c * 3 + 1] * p[1] + w[c * 3 + 2] * p[2];
}

__global__ void addpos_kernel(const float* __restrict__ h)
{
    long idx = (long)blockIdx.x * 256 + threadIdx.x;
    if (idx >= (long)B_ * C_ * N_) return;
    g_hp[idx] = h[idx] + g_pos[idx];
}

// ---------------------------------------------------------------------------
extern "C" void kernel_launch(void* const* d_in, const int* in_sizes, int n_in,
                              void* d_out, int out_size)
{
    (void)in_sizes; (void)n_in; (void)out_size;

    const float* x       = (const float*)d_in[0];
    const float* xyz     = (const float*)d_in[1];
    const float* conv1_w = (const float*)d_in[2];
    const float* convpos = (const float*)d_in[3];
    const float* bn1_g   = (const float*)d_in[4];
    const float* bn1_b   = (const float*)d_in[5];
    const float* bn1_m   = (const float*)d_in[6];
    const float* bn1_v   = (const float*)d_in[7];
    const float* Wqk     = (const float*)d_in[8];
    const float* Wv      = (const float*)d_in[9];
    const float* bv      = (const float*)d_in[10];
    const float* Wt      = (const float*)d_in[11];
    const float* bt      = (const float*)d_in[12];
    const float* bng     = (const float*)d_in[13];
    const float* bnb     = (const float*)d_in[14];
    const float* bnm     = (const float*)d_in[15];
    const float* bnv     = (const float*)d_in[16];
    float* out = (float*)d_out;

    float *pos, *h0, *h1, *hp, *q, *val, *xr, *att, *cs;
    cudaGetSymbolAddress((void**)&pos, g_pos);
    cudaGetSymbolAddress((void**)&h0,  g_h0);
    cudaGetSymbolAddress((void**)&h1,  g_h1);
    cudaGetSymbolAddress((void**)&hp,  g_hp);
    cudaGetSymbolAddress((void**)&q,   g_q);
    cudaGetSymbolAddress((void**)&val, g_val);
    cudaGetSymbolAddress((void**)&xr,  g_xr);
    cudaGetSymbolAddress((void**)&att, g_att);
    cudaGetSymbolAddress((void**)&cs,  g_cs);

    const long SCN = (long)C_ * N_;        // per-batch h stride
    const long SDN = (long)D_ * N_;
    const long SNN = (long)N_ * N_;
    const long elems = (long)B_ * C_ * N_;
    const int  eg = (int)((elems + 255) / 256);

    dim3 blk(256);
    dim3 gC (N_ / 128, C_ / 128, B_);      // (16, 2, 8) for M=256
    dim3 gQ (N_ / 128, 1,        B_);      // M=64
    dim3 gE (N_ / 128, N_ / 128, B_);      // (16, 16, 8)
    dim3 gCS(N_ / 256, N_ / 128, B_);      // (8, 16, 8)

    // pos embedding
    pos_kernel<<<eg, blk>>>(convpos, xyz);

    // h = relu(bn1(conv1_w @ x))
    gemm_kernel<EPI_BN_RELU, false><<<gC, blk>>>(
        conv1_w, 0, C_, C_, x, SCN, nullptr, h0, SCN,
        nullptr, bn1_g, bn1_b, bn1_m, bn1_v, nullptr, nullptr, nullptr, 0);

    float* hcur = h0;
    float* hnxt = h1;

    for (int i = 0; i < 4; i++) {
        // hp = h + pos
        addpos_kernel<<<eg, blk>>>(hcur);

        // q = Wqk[i] @ hp
        gemm_kernel<EPI_BIAS, false><<<gQ, blk>>>(
            Wqk + (long)i * D_ * C_, 0, D_, C_, hp, SCN, nullptr, q, SDN,
            nullptr, nullptr, nullptr, nullptr, nullptr, nullptr, nullptr, nullptr, 0);

        // val = Wv[i] @ hp + bv[i]
        gemm_kernel<EPI_BIAS, false><<<gC, blk>>>(
            Wv + (long)i * C_ * C_, 0, C_, C_, hp, SCN, nullptr, val, SCN,
            bv + i * C_, nullptr, nullptr, nullptr, nullptr, nullptr, nullptr, nullptr, 0);

        // energy = q^T q
        energy_kernel<<<gE, blk>>>(q, att);

        // row softmax (in place)
        softmax_kernel<<<B_ * N_, blk>>>(att);

        // column sums
        zero_kernel<<<(B_ * N_ + 255) / 256, blk>>>(cs, B_ * N_);
        colsum_kernel<<<gCS, blk>>>(att, cs);

        // x_r = (val @ att) / (1e-9 + colsum[m])
        gemm_kernel<EPI_COLSCALE, false><<<gC, blk>>>(
            val, SCN, C_, N_, att, SNN, nullptr, xr, SCN,
            nullptr, nullptr, nullptr, nullptr, nullptr, cs, nullptr, nullptr, 0);

        // h_new = h + relu(bn(Wt[i] @ (h - x_r) + bt[i]));  also write out slice
        gemm_kernel<EPI_T_UPDATE, true><<<gC, blk>>>(
            Wt + (long)i * C_ * C_, 0, C_, C_, hcur, SCN, xr, hnxt, SCN,
            bt + i * C_, bng + i * C_, bnb + i * C_, bnm + i * C_, bnv + i * C_,
            nullptr, hcur, out + (long)i * C_ * N_, (long)4 * C_ * N_);

        float* tmp = hcur; hcur = hnxt; hnxt = tmp;
    }
}

// round 2
// speedup vs baseline: 2.6207x; 2.6207x over previous
#include <cuda_runtime.h>
#include <cstdint>

// ---------------------------------------------------------------------------
// PCT position-embedding + 4 offset-attention SA layers. B=8, C=256, D=64,
// N=2048.  All GEMMs on tensor cores via mma.sync tf32 (operands pre-rounded
// with cvt.rna so in-MMA truncation is exact).
// ---------------------------------------------------------------------------

#define B_   8
#define C_   256
#define D_   64
#define N_   2048

// ---- static device scratch (no runtime allocation allowed) ----
__device__ float g_pos [B_ * C_ * N_];
__device__ float g_h0  [B_ * C_ * N_];
__device__ float g_h1  [B_ * C_ * N_];
__device__ float g_hp  [B_ * C_ * N_];
__device__ float g_xrnd[B_ * C_ * N_];
__device__ float g_q   [B_ * D_ * N_];
__device__ float g_qT  [B_ * N_ * D_];
__device__ float g_val [B_ * C_ * N_];
__device__ float g_xr  [B_ * C_ * N_];
__device__ float g_att [(long long)B_ * N_ * N_];
__device__ float g_wts [655360];   // rounded weights: conv1|Wqk|Wv|Wt

__device__ __forceinline__ float rna_tf32(float x) {
    uint32_t u;
    asm("cvt.rna.tf32.f32 %0, %1;" : "=r"(u) : "f"(x));
    return __uint_as_float(u);
}

// ---------------------------------------------------------------------------
// tf32 tensor-core GEMM: C[M, 2048] = A[M,K] @ B[K, 2048]
// block tile 128x128, k-stage 16, 8 warps (2x4), warp tile 64x32.
// ---------------------------------------------------------------------------
enum { EPI_BN_RELU = 0, EPI_QDUAL = 1, EPI_BIAS_RND = 2, EPI_PLAIN = 3,
       EPI_COLSCALE = 4, EPI_T_UPDATE = 5 };

__device__ __forceinline__ void compute_tile(
    const float (*Asb)[20], const float (*Bsb)[136],
    float acc[4][4][4], int lane, int wm0, int wn0, int g, int tg)
{
#pragma unroll
    for (int ks = 0; ks < 2; ks++) {
        uint32_t a[4][4];
#pragma unroll
        for (int mt = 0; mt < 4; mt++) {
            const float* p = &Asb[wm0 + mt * 16 + (lane & 15)][ks * 8 + (lane >> 4) * 4];
            uint32_t ad = (uint32_t)__cvta_generic_to_shared(p);
            asm volatile("ldmatrix.sync.aligned.m8n8.x4.shared.b16 {%0,%1,%2,%3}, [%4];"
                : "=r"(a[mt][0]), "=r"(a[mt][1]), "=r"(a[mt][2]), "=r"(a[mt][3])
                : "r"(ad));
        }
        uint32_t bf[4][2];
#pragma unroll
        for (int nt = 0; nt < 4; nt++) {
            bf[nt][0] = __float_as_uint(Bsb[ks * 8 + tg    ][wn0 + nt * 8 + g]);
            bf[nt][1] = __float_as_uint(Bsb[ks * 8 + tg + 4][wn0 + nt * 8 + g]);
        }
#pragma unroll
        for (int mt = 0; mt < 4; mt++)
#pragma unroll
            for (int nt = 0; nt < 4; nt++) {
                asm volatile(
                    "mma.sync.aligned.m16n8k8.row.col.f32.tf32.tf32.f32 "
                    "{%0,%1,%2,%3}, {%4,%5,%6,%7}, {%8,%9}, {%0,%1,%2,%3};"
                    : "+f"(acc[mt][nt][0]), "+f"(acc[mt][nt][1]),
                      "+f"(acc[mt][nt][2]), "+f"(acc[mt][nt][3])
                    : "r"(a[mt][0]), "r"(a[mt][1]), "r"(a[mt][2]), "r"(a[mt][3]),
                      "r"(bf[nt][0]), "r"(bf[nt][1]));
            }
    }
}

template <int EPI, bool BSUB>
__global__ void __launch_bounds__(256, 2)
tgemm(const float* __restrict__ A, long aStride, int M, int K,
      const float* __restrict__ Bm, long bStride,
      const float* __restrict__ Bsub,
      float* __restrict__ Cm, long cStride,
      const float* __restrict__ bias,
      const float* __restrict__ bng, const float* __restrict__ bnb,
      const float* __restrict__ bnm, const float* __restrict__ bnv,
      const float* __restrict__ hres,
      float* __restrict__ out2, long out2Stride,
      float* __restrict__ qT)
{
    __shared__ float As[2][128][20];
    __shared__ float Bs[2][16][136];
    __shared__ float csred[8][128];
    __shared__ float csb[128];

    const int bz = blockIdx.z;
    const float* Ab = A + (long)bz * aStride;
    const float* Bb = Bm + (long)bz * bStride;
    const float* Sb = BSUB ? (Bsub + (long)bz * bStride) : nullptr;

    const int m0 = blockIdx.y * 128;
    const int n0 = blockIdx.x * 128;
    const int t  = threadIdx.x;
    const int lane = t & 31;
    const int w    = t >> 5;
    const int g  = lane >> 2, tg = lane & 3;
    const int wm0 = (w >> 2) * 64, wn0 = (w & 3) * 32;

    float acc[4][4][4];
#pragma unroll
    for (int i = 0; i < 4; i++)
#pragma unroll
        for (int j = 0; j < 4; j++)
#pragma unroll
            for (int k = 0; k < 4; k++) acc[i][j][k] = 0.f;

    float csum[4] = {0.f, 0.f, 0.f, 0.f};

    const int aR0 = t >> 2,  aC = (t & 3) * 4;
    const int bR0 = t >> 5,  bC = (t & 31) * 4;
    const int nStages = K >> 4;

    if (!BSUB) {
        // prologue: stage 0
        {
#pragma unroll
            for (int h = 0; h < 2; h++) {
                int row = aR0 + h * 64;
                if (m0 + row < M) {
                    uint32_t dst = (uint32_t)__cvta_generic_to_shared(&As[0][row][aC]);
                    const float* src = Ab + (long)(m0 + row) * K + aC;
                    asm volatile("cp.async.cg.shared.global [%0], [%1], 16;" :: "r"(dst), "l"(src));
                }
            }
#pragma unroll
            for (int h = 0; h < 2; h++) {
                int row = bR0 + h * 8;
                uint32_t dst = (uint32_t)__cvta_generic_to_shared(&Bs[0][row][bC]);
                const float* src = Bb + (long)row * N_ + n0 + bC;
                asm volatile("cp.async.cg.shared.global [%0], [%1], 16;" :: "r"(dst), "l"(src));
            }
            asm volatile("cp.async.commit_group;");
        }
        for (int s = 0; s < nStages; s++) {
            const int cur = s & 1;
            if (s + 1 < nStages) {
                const int k0 = (s + 1) * 16, buf = (s + 1) & 1;
#pragma unroll
                for (int h = 0; h < 2; h++) {
                    int row = aR0 + h * 64;
                    if (m0 + row < M) {
                        uint32_t dst = (uint32_t)__cvta_generic_to_shared(&As[buf][row][aC]);
                        const float* src = Ab + (long)(m0 + row) * K + k0 + aC;
                        asm volatile("cp.async.cg.shared.global [%0], [%1], 16;" :: "r"(dst), "l"(src));
                    }
                }
#pragma unroll
                for (int h = 0; h < 2; h++) {
                    int row = bR0 + h * 8;
                    uint32_t dst = (uint32_t)__cvta_generic_to_shared(&Bs[buf][row][bC]);
                    const float* src = Bb + (long)(k0 + row) * N_ + n0 + bC;
                    asm volatile("cp.async.cg.shared.global [%0], [%1], 16;" :: "r"(dst), "l"(src));
                }
            }
            asm volatile("cp.async.commit_group;");
            asm volatile("cp.async.wait_group 1;");
            __syncthreads();

            if (EPI == EPI_COLSCALE) {
#pragma unroll
                for (int h = 0; h < 2; h++) {
                    const float4 v = *reinterpret_cast<const float4*>(&Bs[cur][bR0 + h * 8][bC]);
                    csum[0] += v.x; csum[1] += v.y; csum[2] += v.z; csum[3] += v.w;
                }
            }
            compute_tile(As[cur], Bs[cur], acc, lane, wm0, wn0, g, tg);
            __syncthreads();
        }
    } else {
        for (int s = 0; s < nStages; s++) {
            const int k0 = s * 16;
            __syncthreads();
#pragma unroll
            for (int h = 0; h < 2; h++) {
                int row = aR0 + h * 64;
                if (m0 + row < M)
                    *reinterpret_cast<float4*>(&As[0][row][aC]) =
                        *reinterpret_cast<const float4*>(Ab + (long)(m0 + row) * K + k0 + aC);
            }
#pragma unroll
            for (int h = 0; h < 2; h++) {
                int row = bR0 + h * 8;
                long off = (long)(k0 + row) * N_ + n0 + bC;
                float4 v = *reinterpret_cast<const float4*>(Bb + off);
                float4 u = *reinterpret_cast<const float4*>(Sb + off);
                v.x = rna_tf32(v.x - u.x); v.y = rna_tf32(v.y - u.y);
                v.z = rna_tf32(v.z - u.z); v.w = rna_tf32(v.w - u.w);
                *reinterpret_cast<float4*>(&Bs[0][row][bC]) = v;
            }
            __syncthreads();
            compute_tile(As[0], Bs[0], acc, lane, wm0, wn0, g, tg);
        }
    }

    if (EPI == EPI_COLSCALE) {
        csred[t >> 5][(t & 31) * 4 + 0] = csum[0];
        csred[t >> 5][(t & 31) * 4 + 1] = csum[1];
        csred[t >> 5][(t & 31) * 4 + 2] = csum[2];
        csred[t >> 5][(t & 31) * 4 + 3] = csum[3];
        __syncthreads();
        if (t < 128) {
            float ssum = 0.f;
#pragma unroll
            for (int r = 0; r < 8; r++) ssum += csred[r][t];
            csb[t] = 1.f / (1e-9f + ssum);
        }
        __syncthreads();
    }

    float* Cb = Cm + (long)bz * cStride;
#pragma unroll
    for (int mt = 0; mt < 4; mt++) {
        const int r0 = m0 + wm0 + mt * 16 + g;
        const int r1 = r0 + 8;
        float s0 = 1.f, sh0 = 0.f, b0v = 0.f, s1 = 1.f, sh1 = 0.f, b1v = 0.f;
        if (EPI == EPI_BN_RELU || EPI == EPI_T_UPDATE) {
            if (r0 < M) { float inv = rsqrtf(bnv[r0] + 1e-5f); s0 = bng[r0] * inv; sh0 = bnb[r0] - bnm[r0] * s0; }
            if (r1 < M) { float inv = rsqrtf(bnv[r1] + 1e-5f); s1 = bng[r1] * inv; sh1 = bnb[r1] - bnm[r1] * s1; }
        }
        if (EPI == EPI_BIAS_RND || EPI == EPI_T_UPDATE) {
            if (r0 < M) b0v = bias[r0];
            if (r1 < M) b1v = bias[r1];
        }
#pragma unroll
        for (int nt = 0; nt < 4; nt++) {
            const int cb = n0 + wn0 + nt * 8 + 2 * tg;
            float v00 = acc[mt][nt][0], v01 = acc[mt][nt][1];
            float v10 = acc[mt][nt][2], v11 = acc[mt][nt][3];
            if (EPI == EPI_BN_RELU) {
                v00 = fmaxf(fmaf(v00, s0, sh0), 0.f); v01 = fmaxf(fmaf(v01, s0, sh0), 0.f);
                v10 = fmaxf(fmaf(v10, s1, sh1), 0.f); v11 = fmaxf(fmaf(v11, s1, sh1), 0.f);
            } else if (EPI == EPI_BIAS_RND) {
                v00 = rna_tf32(v00 + b0v); v01 = rna_tf32(v01 + b0v);
                v10 = rna_tf32(v10 + b1v); v11 = rna_tf32(v11 + b1v);
            } else if (EPI == EPI_QDUAL) {
                v00 = rna_tf32(v00); v01 = rna_tf32(v01);
                v10 = rna_tf32(v10); v11 = rna_tf32(v11);
            } else if (EPI == EPI_COLSCALE) {
                float i0 = csb[cb - n0], i1 = csb[cb - n0 + 1];
                v00 *= i0; v01 *= i1; v10 *= i0; v11 *= i1;
            } else if (EPI == EPI_T_UPDATE) {
                v00 = fmaxf(fmaf(v00 + b0v, s0, sh0), 0.f); v01 = fmaxf(fmaf(v01 + b0v, s0, sh0), 0.f);
                v10 = fmaxf(fmaf(v10 + b1v, s1, sh1), 0.f); v11 = fmaxf(fmaf(v11 + b1v, s1, sh1), 0.f);
            }

            if (EPI == EPI_T_UPDATE) {
                const float* hr = hres + (long)bz * cStride;
                float* o2 = out2 + (long)bz * out2Stride;
                if (r0 < M) {
                    float2 h2 = *reinterpret_cast<const float2*>(hr + (long)r0 * N_ + cb);
                    float2 o = make_float2(v00 + h2.x, v01 + h2.y);
                    *reinterpret_cast<float2*>(Cb + (long)r0 * N_ + cb) = o;
                    *reinterpret_cast<float2*>(o2 + (long)r0 * N_ + cb) = o;
                }
                if (r1 < M) {
                    float2 h2 = *reinterpret_cast<const float2*>(hr + (long)r1 * N_ + cb);
                    float2 o = make_float2(v10 + h2.x, v11 + h2.y);
                    *reinterpret_cast<float2*>(Cb + (long)r1 * N_ + cb) = o;
                    *reinterpret_cast<float2*>(o2 + (long)r1 * N_ + cb) = o;
                }
            } else {
                if (r0 < M)
                    *reinterpret_cast<float2*>(Cb + (long)r0 * N_ + cb) = make_float2(v00, v01);
                if (r1 < M)
                    *reinterpret_cast<float2*>(Cb + (long)r1 * N_ + cb) = make_float2(v10, v11);
                if (EPI == EPI_QDUAL) {
                    float* qTb = qT + (long)bz * ((long)N_ * D_);
                    if (r0 < M) { qTb[(long)cb * D_ + r0] = v00; qTb[(long)(cb + 1) * D_ + r0] = v01; }
                    if (r1 < M) { qTb[(long)cb * D_ + r1] = v10; qTb[(long)(cb + 1) * D_ + r1] = v11; }
                }
            }
        }
    }
}

// ---------------------------------------------------------------------------
// Row softmax over last dim (in place), writes tf32-rounded values.
// ---------------------------------------------------------------------------
__global__ void __launch_bounds__(256)
softmax_kernel(float* __restrict__ E)
{
    long row = blockIdx.x;
    float* r = E + row * (long)N_;
    const int t = threadIdx.x;

    float v[8];
    float mx = -3.4e38f;
#pragma unroll
    for (int i = 0; i < 8; i++) { v[i] = r[t + 256 * i]; mx = fmaxf(mx, v[i]); }

    __shared__ float red[8];
#pragma unroll
    for (int o = 16; o > 0; o >>= 1) mx = fmaxf(mx, __shfl_xor_sync(0xffffffffu, mx, o));
    if ((t & 31) == 0) red[t >> 5] = mx;
    __syncthreads();
    float bm = red[0];
#pragma unroll
    for (int w = 1; w < 8; w++) bm = fmaxf(bm, red[w]);
    __syncthreads();

    float sum = 0.f;
#pragma unroll
    for (int i = 0; i < 8; i++) { v[i] = expf(v[i] - bm); sum += v[i]; }
#pragma unroll
    for (int o = 16; o > 0; o >>= 1) sum += __shfl_xor_sync(0xffffffffu, sum, o);
    if ((t & 31) == 0) red[t >> 5] = sum;
    __syncthreads();
    float tot = 0.f;
#pragma unroll
    for (int w = 0; w < 8; w++) tot += red[w];

    float inv = 1.f / tot;
#pragma unroll
    for (int i = 0; i < 8; i++) r[t + 256 * i] = rna_tf32(v[i] * inv);
}

// ---------------------------------------------------------------------------
__global__ void round_copy_kernel(const float* __restrict__ in, float* __restrict__ out, long n)
{
    long i = (long)blockIdx.x * 256 + threadIdx.x;
    if (i < n) out[i] = rna_tf32(in[i]);
}

__global__ void pos_kernel(const float* __restrict__ w, const float* __restrict__ xyz)
{
    long idx = (long)blockIdx.x * 256 + threadIdx.x;
    if (idx >= (long)B_ * C_ * N_) return;
    int n = (int)(idx % N_);
    int c = (int)((idx / N_) % C_);
    int b = (int)(idx / ((long)C_ * N_));
    const float* p = xyz + ((long)b * N_ + n) * 3;
    g_pos[idx] = w[c * 3 + 0] * p[0] + w[c * 3 + 1] * p[1] + w[c * 3 + 2] * p[2];
}

__global__ void addpos_kernel(const float* __restrict__ h)
{
    long idx = (long)blockIdx.x * 256 + threadIdx.x;
    if (idx >= (long)B_ * C_ * N_) return;
    g_hp[idx] = rna_tf32(h[idx] + g_pos[idx]);
}

// ---------------------------------------------------------------------------
extern "C" void kernel_launch(void* const* d_in, const int* in_sizes, int n_in,
                              void* d_out, int out_size)
{
    (void)in_sizes; (void)n_in; (void)out_size;

    const float* x       = (const float*)d_in[0];
    const float* xyz     = (const float*)d_in[1];
    const float* conv1_w = (const float*)d_in[2];
    const float* convpos = (const float*)d_in[3];
    const float* bn1_g   = (const float*)d_in[4];
    const float* bn1_b   = (const float*)d_in[5];
    const float* bn1_m   = (const float*)d_in[6];
    const float* bn1_v   = (const float*)d_in[7];
    const float* Wqk     = (const float*)d_in[8];
    const float* Wv      = (const float*)d_in[9];
    const float* bv      = (const float*)d_in[10];
    const float* Wt      = (const float*)d_in[11];
    const float* bt      = (const float*)d_in[12];
    const float* bng     = (const float*)d_in[13];
    const float* bnb     = (const float*)d_in[14];
    const float* bnm     = (const float*)d_in[15];
    const float* bnv     = (const float*)d_in[16];
    float* out = (float*)d_out;

    float *pos, *h0, *h1, *hp, *xrnd, *q, *qT, *val, *xr, *att, *wts;
    cudaGetSymbolAddress((void**)&pos,  g_pos);
    cudaGetSymbolAddress((void**)&h0,   g_h0);
    cudaGetSymbolAddress((void**)&h1,   g_h1);
    cudaGetSymbolAddress((void**)&hp,   g_hp);
    cudaGetSymbolAddress((void**)&xrnd, g_xrnd);
    cudaGetSymbolAddress((void**)&q,    g_q);
    cudaGetSymbolAddress((void**)&qT,   g_qT);
    cudaGetSymbolAddress((void**)&val,  g_val);
    cudaGetSymbolAddress((void**)&xr,   g_xr);
    cudaGetSymbolAddress((void**)&att,  g_att);
    cudaGetSymbolAddress((void**)&wts,  g_wts);

    const long SCN = (long)C_ * N_;
    const long SDN = (long)D_ * N_;
    const long SNN = (long)N_ * N_;
    const long elems = (long)B_ * C_ * N_;
    const int  eg = (int)((elems + 255) / 256);

    // rounded-weight offsets in g_wts
    float* w_conv1 = wts;
    float* w_qk    = wts + 65536;
    float* w_v     = wts + 131072;
    float* w_t     = wts + 393216;

    dim3 blk(256);
    dim3 gC(N_ / 128, 2, B_);        // M=256
    dim3 gQ(N_ / 128, 1, B_);        // M=64
    dim3 gE(N_ / 128, N_ / 128, B_); // M=N=2048

    // one-time operand rounding
    round_copy_kernel<<<(65536 + 255) / 256, blk>>>(conv1_w, w_conv1, 65536);
    round_copy_kernel<<<(65536 + 255) / 256, blk>>>(Wqk,     w_qk,    65536);
    round_copy_kernel<<<(262144 + 255) / 256, blk>>>(Wv,     w_v,     262144);
    round_copy_kernel<<<(262144 + 255) / 256, blk>>>(Wt,     w_t,     262144);
    round_copy_kernel<<<eg, blk>>>(x, xrnd, elems);

    pos_kernel<<<eg, blk>>>(convpos, xyz);

    // h = relu(bn1(conv1_w @ x))
    tgemm<EPI_BN_RELU, false><<<gC, blk>>>(
        w_conv1, 0, C_, C_, xrnd, SCN, nullptr, h0, SCN,
        nullptr, bn1_g, bn1_b, bn1_m, bn1_v, nullptr, nullptr, 0, nullptr);

    float* hcur = h0;
    float* hnxt = h1;

    for (int i = 0; i < 4; i++) {
        addpos_kernel<<<eg, blk>>>(hcur);

        // q = Wqk[i] @ hp      (writes rounded q and qT)
        tgemm<EPI_QDUAL, false><<<gQ, blk>>>(
            w_qk + (long)i * D_ * C_, 0, D_, C_, hp, SCN, nullptr, q, SDN,
            nullptr, nullptr, nullptr, nullptr, nullptr, nullptr, nullptr, 0, qT);

        // val = Wv[i] @ hp + bv[i]   (rounded)
        tgemm<EPI_BIAS_RND, false><<<gC, blk>>>(
            w_v + (long)i * C_ * C_, 0, C_, C_, hp, SCN, nullptr, val, SCN,
            bv + i * C_, nullptr, nullptr, nullptr, nullptr, nullptr, nullptr, 0, nullptr);

        // energy = qT @ q
        tgemm<EPI_PLAIN, false><<<gE, blk>>>(
            qT, SDN, N_, D_, q, SDN, nullptr, att, SNN,
            nullptr, nullptr, nullptr, nullptr, nullptr, nullptr, nullptr, 0, nullptr);

        softmax_kernel<<<B_ * N_, blk>>>(att);

        // x_r = (val @ att) * 1/(1e-9 + colsum)   (colsum fused)
        tgemm<EPI_COLSCALE, false><<<gC, blk>>>(
            val, SCN, C_, N_, att, SNN, nullptr, xr, SCN,
            nullptr, nullptr, nullptr, nullptr, nullptr, nullptr, nullptr, 0, nullptr);

        // h_new = h + relu(bn(Wt[i] @ rna(h - xr) + bt[i])); dual store
        tgemm<EPI_T_UPDATE, true><<<gC, blk>>>(
            w_t + (long)i * C_ * C_, 0, C_, C_, hcur, SCN, xr, hnxt, SCN,
            bt + i * C_, bng + i * C_, bnb + i * C_, bnm + i * C_, bnv + i * C_,
            hcur, out + (long)i * C_ * N_, (long)4 * C_ * N_, nullptr);

        float* tmp = hcur; hcur = hnxt; hnxt = tmp;
    }
}

// round 3
// speedup vs baseline: 2.6808x; 1.0229x over previous
#include <cuda_runtime.h>
#include <cstdint>

// ---------------------------------------------------------------------------
// PCT position-embedding + 4 offset-attention SA layers. B=8, C=256, D=64,
// N=2048. GEMMs on tensor cores (mma.sync tf32, operands pre-rounded rna).
// ---------------------------------------------------------------------------

#define B_   8
#define C_   256
#define D_   64
#define N_   2048

__device__ float g_pos [B_ * C_ * N_];
__device__ float g_h0  [B_ * C_ * N_];
__device__ float g_h1  [B_ * C_ * N_];
__device__ float g_hp  [B_ * C_ * N_];
__device__ float g_xrnd[B_ * C_ * N_];
__device__ float g_q   [B_ * D_ * N_];
__device__ float g_qT  [B_ * N_ * D_];
__device__ float g_val [B_ * C_ * N_];
__device__ float g_d   [B_ * C_ * N_];      // rna(h - xr)
__device__ float g_att [(long long)B_ * N_ * N_];
__device__ float g_wts [655360];            // conv1 | per-layer [Wqk;Wv] | Wt

__device__ __forceinline__ float rna_tf32(float x) {
    uint32_t u;
    asm("cvt.rna.tf32.f32 %0, %1;" : "=r"(u) : "f"(x));
    return __uint_as_float(u);
}

// ---------------------------------------------------------------------------
// one prep kernel: rounds all weights + x, computes pos. Single launch so the
// ncu skip-count lands on the xr GEMM.
// ---------------------------------------------------------------------------
#define SEG_W1   65536L
#define SEG_QV   327680L               // 4 * (64+256)*256
#define SEG_WT   262144L
#define SEG_X    ((long)B_ * C_ * N_)
#define PREP_TOT (SEG_W1 + SEG_QV + SEG_WT + SEG_X + SEG_X)

__global__ void prep_kernel(const float* __restrict__ conv1_w,
                            const float* __restrict__ Wqk,
                            const float* __restrict__ Wv,
                            const float* __restrict__ Wt,
                            const float* __restrict__ x,
                            const float* __restrict__ convpos,
                            const float* __restrict__ xyz)
{
    long i = (long)blockIdx.x * 256 + threadIdx.x;
    if (i >= PREP_TOT) return;
    if (i < SEG_W1) {
        g_wts[i] = rna_tf32(conv1_w[i]);
    } else if (i < SEG_W1 + SEG_QV) {
        long j = i - SEG_W1;
        int layer = (int)(j / 81920);
        long o = j % 81920;
        float v = (o < 16384) ? Wqk[(long)layer * 16384 + o]
                              : Wv[(long)layer * 65536 + (o - 16384)];
        g_wts[i] = rna_tf32(v);
    } else if (i < SEG_W1 + SEG_QV + SEG_WT) {
        g_wts[i] = rna_tf32(Wt[i - SEG_W1 - SEG_QV]);
    } else if (i < SEG_W1 + SEG_QV + SEG_WT + SEG_X) {
        long j = i - SEG_W1 - SEG_QV - SEG_WT;
        g_xrnd[j] = rna_tf32(x[j]);
    } else {
        long j = i - SEG_W1 - SEG_QV - SEG_WT - SEG_X;
        int n = (int)(j % N_);
        int c = (int)((j / N_) % C_);
        int b = (int)(j / ((long)C_ * N_));
        const float* p = xyz + ((long)b * N_ + n) * 3;
        g_pos[j] = convpos[c * 3 + 0] * p[0] + convpos[c * 3 + 1] * p[1]
                 + convpos[c * 3 + 2] * p[2];
    }
}

// ---------------------------------------------------------------------------
// tf32 tensor-core GEMM: C[M, 2048] = A[M,K] @ B[K, 2048]
// block tile 128x128, k-stage 16, double buffered cp.async, 8 warps (2x4).
// ---------------------------------------------------------------------------
enum { EPI_BN_RELU = 0, EPI_QVAL = 1, EPI_PLAIN = 2, EPI_COLSCALE = 3,
       EPI_T_UPDATE = 4 };

__device__ __forceinline__ void compute_tile(
    const float (*Asb)[20], const float (*Bsb)[136],
    float acc[4][4][4], int lane, int wm0, int wn0, int g, int tg)
{
#pragma unroll
    for (int ks = 0; ks < 2; ks++) {
        uint32_t a[4][4];
#pragma unroll
        for (int mt = 0; mt < 4; mt++) {
            const float* p = &Asb[wm0 + mt * 16 + (lane & 15)][ks * 8 + (lane >> 4) * 4];
            uint32_t ad = (uint32_t)__cvta_generic_to_shared(p);
            asm volatile("ldmatrix.sync.aligned.m8n8.x4.shared.b16 {%0,%1,%2,%3}, [%4];"
                : "=r"(a[mt][0]), "=r"(a[mt][1]), "=r"(a[mt][2]), "=r"(a[mt][3])
                : "r"(ad));
        }
        uint32_t bf[4][2];
#pragma unroll
        for (int nt = 0; nt < 4; nt++) {
            bf[nt][0] = __float_as_uint(Bsb[ks * 8 + tg    ][wn0 + nt * 8 + g]);
            bf[nt][1] = __float_as_uint(Bsb[ks * 8 + tg + 4][wn0 + nt * 8 + g]);
        }
#pragma unroll
        for (int mt = 0; mt < 4; mt++)
#pragma unroll
            for (int nt = 0; nt < 4; nt++) {
                asm volatile(
                    "mma.sync.aligned.m16n8k8.row.col.f32.tf32.tf32.f32 "
                    "{%0,%1,%2,%3}, {%4,%5,%6,%7}, {%8,%9}, {%0,%1,%2,%3};"
                    : "+f"(acc[mt][nt][0]), "+f"(acc[mt][nt][1]),
                      "+f"(acc[mt][nt][2]), "+f"(acc[mt][nt][3])
                    : "r"(a[mt][0]), "r"(a[mt][1]), "r"(a[mt][2]), "r"(a[mt][3]),
                      "r"(bf[nt][0]), "r"(bf[nt][1]));
            }
    }
}

template <int EPI>
__global__ void __launch_bounds__(256, 2)
tgemm(const float* __restrict__ A, long aStride, int M, int K,
      const float* __restrict__ Bm, long bStride,
      float* __restrict__ Cm, long cStride,
      const float* __restrict__ bias,
      const float* __restrict__ bng, const float* __restrict__ bnb,
      const float* __restrict__ bnm, const float* __restrict__ bnv,
      const float* __restrict__ hres, long hresStride,
      const float* __restrict__ posB,
      float* __restrict__ hpOut,
      float* __restrict__ out2, long out2Stride,
      float* __restrict__ qB, float* __restrict__ qTB)
{
    __shared__ float As[2][128][20];
    __shared__ float Bs[2][16][136];
    __shared__ float csred[8][128];
    __shared__ float csb[128];

    const int bz = blockIdx.z;
    const float* Ab = A + (long)bz * aStride;
    const float* Bb = Bm + (long)bz * bStride;

    const int m0 = blockIdx.y * 128;
    const int n0 = blockIdx.x * 128;
    const int t  = threadIdx.x;
    const int lane = t & 31;
    const int w    = t >> 5;
    const int g  = lane >> 2, tg = lane & 3;
    const int wm0 = (w >> 2) * 64, wn0 = (w & 3) * 32;

    float acc[4][4][4];
#pragma unroll
    for (int i = 0; i < 4; i++)
#pragma unroll
        for (int j = 0; j < 4; j++)
#pragma unroll
            for (int k = 0; k < 4; k++) acc[i][j][k] = 0.f;

    float csum[4] = {0.f, 0.f, 0.f, 0.f};

    const int aR0 = t >> 2,  aC = (t & 3) * 4;
    const int bR0 = t >> 5,  bC = (t & 31) * 4;
    const int nStages = K >> 4;

    // prologue: stage 0
    {
#pragma unroll
        for (int h = 0; h < 2; h++) {
            int row = aR0 + h * 64;
            if (m0 + row < M) {
                uint32_t dst = (uint32_t)__cvta_generic_to_shared(&As[0][row][aC]);
                const float* src = Ab + (long)(m0 + row) * K + aC;
                asm volatile("cp.async.cg.shared.global [%0], [%1], 16;" :: "r"(dst), "l"(src));
            }
        }
#pragma unroll
        for (int h = 0; h < 2; h++) {
            int row = bR0 + h * 8;
            uint32_t dst = (uint32_t)__cvta_generic_to_shared(&Bs[0][row][bC]);
            const float* src = Bb + (long)row * N_ + n0 + bC;
            asm volatile("cp.async.cg.shared.global [%0], [%1], 16;" :: "r"(dst), "l"(src));
        }
        asm volatile("cp.async.commit_group;");
    }
    for (int s = 0; s < nStages; s++) {
        const int cur = s & 1;
        if (s + 1 < nStages) {
            const int k0 = (s + 1) * 16, buf = (s + 1) & 1;
#pragma unroll
            for (int h = 0; h < 2; h++) {
                int row = aR0 + h * 64;
                if (m0 + row < M) {
                    uint32_t dst = (uint32_t)__cvta_generic_to_shared(&As[buf][row][aC]);
                    const float* src = Ab + (long)(m0 + row) * K + k0 + aC;
                    asm volatile("cp.async.cg.shared.global [%0], [%1], 16;" :: "r"(dst), "l"(src));
                }
            }
#pragma unroll
            for (int h = 0; h < 2; h++) {
                int row = bR0 + h * 8;
                uint32_t dst = (uint32_t)__cvta_generic_to_shared(&Bs[buf][row][bC]);
                const float* src = Bb + (long)(k0 + row) * N_ + n0 + bC;
                asm volatile("cp.async.cg.shared.global [%0], [%1], 16;" :: "r"(dst), "l"(src));
            }
        }
        asm volatile("cp.async.commit_group;");
        asm volatile("cp.async.wait_group 1;");
        __syncthreads();

        if (EPI == EPI_COLSCALE) {
#pragma unroll
            for (int h = 0; h < 2; h++) {
                const float4 v = *reinterpret_cast<const float4*>(&Bs[cur][bR0 + h * 8][bC]);
                csum[0] += v.x; csum[1] += v.y; csum[2] += v.z; csum[3] += v.w;
            }
        }
        compute_tile(As[cur], Bs[cur], acc, lane, wm0, wn0, g, tg);
        __syncthreads();
    }

    if (EPI == EPI_COLSCALE) {
        csred[t >> 5][(t & 31) * 4 + 0] = csum[0];
        csred[t >> 5][(t & 31) * 4 + 1] = csum[1];
        csred[t >> 5][(t & 31) * 4 + 2] = csum[2];
        csred[t >> 5][(t & 31) * 4 + 3] = csum[3];
        __syncthreads();
        if (t < 128) {
            float ssum = 0.f;
#pragma unroll
            for (int r = 0; r < 8; r++) ssum += csred[r][t];
            csb[t] = 1.f / (1e-9f + ssum);
        }
        __syncthreads();
    }

    float* Cb = Cm + (long)bz * cStride;
#pragma unroll
    for (int mt = 0; mt < 4; mt++) {
#pragma unroll
        for (int half = 0; half < 2; half++) {
            const int r = m0 + wm0 + mt * 16 + g + half * 8;
            if (r >= M) continue;

            float sc = 1.f, sh = 0.f, bsv = 0.f;
            if (EPI == EPI_BN_RELU || EPI == EPI_T_UPDATE) {
                float inv = rsqrtf(bnv[r] + 1e-5f);
                sc = bng[r] * inv; sh = bnb[r] - bnm[r] * sc;
            }
            if (EPI == EPI_T_UPDATE) bsv = bias[r];
            if (EPI == EPI_QVAL && r >= 64) bsv = bias[r - 64];

#pragma unroll
            for (int nt = 0; nt < 4; nt++) {
                const int cb = n0 + wn0 + nt * 8 + 2 * tg;
                float v0 = acc[mt][nt][half * 2 + 0];
                float v1 = acc[mt][nt][half * 2 + 1];
                long rowoff = (long)r * N_ + cb;

                if (EPI == EPI_BN_RELU) {
                    v0 = fmaxf(fmaf(v0, sc, sh), 0.f);
                    v1 = fmaxf(fmaf(v1, sc, sh), 0.f);
                    *reinterpret_cast<float2*>(Cb + rowoff) = make_float2(v0, v1);
                    const float* pb = posB + (long)bz * hresStride;
                    float2 p2 = *reinterpret_cast<const float2*>(pb + rowoff);
                    float* hb = hpOut + (long)bz * hresStride;
                    *reinterpret_cast<float2*>(hb + rowoff) =
                        make_float2(rna_tf32(v0 + p2.x), rna_tf32(v1 + p2.y));
                } else if (EPI == EPI_QVAL) {
                    if (r < 64) {
                        float q0 = rna_tf32(v0), q1 = rna_tf32(v1);
                        float* qb = qB + (long)bz * ((long)D_ * N_);
                        *reinterpret_cast<float2*>(qb + (long)r * N_ + cb) = make_float2(q0, q1);
                        float* qt = qTB + (long)bz * ((long)N_ * D_);
                        qt[(long)cb * D_ + r]       = q0;
                        qt[(long)(cb + 1) * D_ + r] = q1;
                    } else {
                        long vo = (long)(r - 64) * N_ + cb;
                        *reinterpret_cast<float2*>(Cb + vo) =
                            make_float2(rna_tf32(v0 + bsv), rna_tf32(v1 + bsv));
                    }
                } else if (EPI == EPI_PLAIN) {
                    *reinterpret_cast<float2*>(Cb + rowoff) = make_float2(v0, v1);
                } else if (EPI == EPI_COLSCALE) {
                    float i0 = csb[cb - n0], i1 = csb[cb - n0 + 1];
                    const float* hb = hres + (long)bz * hresStride;
                    float2 h2 = *reinterpret_cast<const float2*>(hb + rowoff);
                    *reinterpret_cast<float2*>(Cb + rowoff) =
                        make_float2(rna_tf32(h2.x - v0 * i0), rna_tf32(h2.y - v1 * i1));
                } else { // EPI_T_UPDATE
                    v0 = fmaxf(fmaf(v0 + bsv, sc, sh), 0.f);
                    v1 = fmaxf(fmaf(v1 + bsv, sc, sh), 0.f);
                    const float* hb = hres + (long)bz * hresStride;
                    float2 h2 = *reinterpret_cast<const float2*>(hb + rowoff);
                    float o0 = v0 + h2.x, o1 = v1 + h2.y;
                    *reinterpret_cast<float2*>(Cb + rowoff) = make_float2(o0, o1);
                    float* ob = out2 + (long)bz * out2Stride;
                    *reinterpret_cast<float2*>(ob + rowoff) = make_float2(o0, o1);
                    const float* pb = posB + (long)bz * hresStride;
                    float2 p2 = *reinterpret_cast<const float2*>(pb + rowoff);
                    float* hb2 = hpOut + (long)bz * hresStride;
                    *reinterpret_cast<float2*>(hb2 + rowoff) =
                        make_float2(rna_tf32(o0 + p2.x), rna_tf32(o1 + p2.y));
                }
            }
        }
    }
}

// ---------------------------------------------------------------------------
// Row softmax (in place), float4 + __expf, writes tf32-rounded values.
// ---------------------------------------------------------------------------
__global__ void __launch_bounds__(256)
softmax_kernel(float* __restrict__ E)
{
    long row = blockIdx.x;
    float4* r = reinterpret_cast<float4*>(E + row * (long)N_);
    const int t = threadIdx.x;

    float4 va = r[t];
    float4 vb = r[t + 256];
    float mx = fmaxf(fmaxf(fmaxf(va.x, va.y), fmaxf(va.z, va.w)),
                     fmaxf(fmaxf(vb.x, vb.y), fmaxf(vb.z, vb.w)));

    __shared__ float red[8];
#pragma unroll
    for (int o = 16; o > 0; o >>= 1) mx = fmaxf(mx, __shfl_xor_sync(0xffffffffu, mx, o));
    if ((t & 31) == 0) red[t >> 5] = mx;
    __syncthreads();
    float bm = red[0];
#pragma unroll
    for (int w = 1; w < 8; w++) bm = fmaxf(bm, red[w]);
    __syncthreads();

    va.x = __expf(va.x - bm); va.y = __expf(va.y - bm);
    va.z = __expf(va.z - bm); va.w = __expf(va.w - bm);
    vb.x = __expf(vb.x - bm); vb.y = __expf(vb.y - bm);
    vb.z = __expf(vb.z - bm); vb.w = __expf(vb.w - bm);
    float sum = va.x + va.y + va.z + va.w + vb.x + vb.y + vb.z + vb.w;
#pragma unroll
    for (int o = 16; o > 0; o >>= 1) sum += __shfl_xor_sync(0xffffffffu, sum, o);
    if ((t & 31) == 0) red[t >> 5] = sum;
    __syncthreads();
    float tot = 0.f;
#pragma unroll
    for (int w = 0; w < 8; w++) tot += red[w];

    float inv = 1.f / tot;
    va.x = rna_tf32(va.x * inv); va.y = rna_tf32(va.y * inv);
    va.z = rna_tf32(va.z * inv); va.w = rna_tf32(va.w * inv);
    vb.x = rna_tf32(vb.x * inv); vb.y = rna_tf32(vb.y * inv);
    vb.z = rna_tf32(vb.z * inv); vb.w = rna_tf32(vb.w * inv);
    r[t] = va;
    r[t + 256] = vb;
}

// ---------------------------------------------------------------------------
extern "C" void kernel_launch(void* const* d_in, const int* in_sizes, int n_in,
                              void* d_out, int out_size)
{
    (void)in_sizes; (void)n_in; (void)out_size;

    const float* x       = (const float*)d_in[0];
    const float* xyz     = (const float*)d_in[1];
    const float* conv1_w = (const float*)d_in[2];
    const float* convpos = (const float*)d_in[3];
    const float* bn1_g   = (const float*)d_in[4];
    const float* bn1_b   = (const float*)d_in[5];
    const float* bn1_m   = (const float*)d_in[6];
    const float* bn1_v   = (const float*)d_in[7];
    const float* Wqk     = (const float*)d_in[8];
    const float* Wv      = (const float*)d_in[9];
    const float* bv      = (const float*)d_in[10];
    const float* Wt      = (const float*)d_in[11];
    const float* bt      = (const float*)d_in[12];
    const float* bng     = (const float*)d_in[13];
    const float* bnb     = (const float*)d_in[14];
    const float* bnm     = (const float*)d_in[15];
    const float* bnv     = (const float*)d_in[16];
    float* out = (float*)d_out;

    float *pos, *h0, *h1, *hp, *xrnd, *q, *qT, *val, *dbuf, *att, *wts;
    cudaGetSymbolAddress((void**)&pos,  g_pos);
    cudaGetSymbolAddress((void**)&h0,   g_h0);
    cudaGetSymbolAddress((void**)&h1,   g_h1);
    cudaGetSymbolAddress((void**)&hp,   g_hp);
    cudaGetSymbolAddress((void**)&xrnd, g_xrnd);
    cudaGetSymbolAddress((void**)&q,    g_q);
    cudaGetSymbolAddress((void**)&qT,   g_qT);
    cudaGetSymbolAddress((void**)&val,  g_val);
    cudaGetSymbolAddress((void**)&dbuf, g_d);
    cudaGetSymbolAddress((void**)&att,  g_att);
    cudaGetSymbolAddress((void**)&wts,  g_wts);

    const long SCN = (long)C_ * N_;
    const long SDN = (long)D_ * N_;
    const long SNN = (long)N_ * N_;
    const long SND = (long)N_ * D_;

    float* w_conv1 = wts;
    float* w_qv    = wts + SEG_W1;            // per layer 320*256
    float* w_t     = wts + SEG_W1 + SEG_QV;

    dim3 blk(256);
    dim3 gC (N_ / 128, 2, B_);        // M=256
    dim3 gQV(N_ / 128, 3, B_);        // M=320
    dim3 gE (N_ / 128, N_ / 128, B_); // M=N=2048

    // [0] prep
    prep_kernel<<<(int)((PREP_TOT + 255) / 256), blk>>>(conv1_w, Wqk, Wv, Wt, x,
                                                        convpos, xyz);

    // [1] conv1: h0 = relu(bn1(conv1_w @ x));  hp = rna(h0 + pos)
    tgemm<EPI_BN_RELU><<<gC, blk>>>(
        w_conv1, 0, C_, C_, xrnd, SCN, h0, SCN,
        nullptr, bn1_g, bn1_b, bn1_m, bn1_v,
        nullptr, SCN, pos, hp, nullptr, 0, nullptr, nullptr);

    float* hcur = h0;
    float* hnxt = h1;

    for (int i = 0; i < 4; i++) {
        // qval: [q;val] = [Wqk;Wv] @ hp  (q rounded + qT; val = rna(.+bv))
        tgemm<EPI_QVAL><<<gQV, blk>>>(
            w_qv + (long)i * 81920, 0, 320, C_, hp, SCN, val, SCN,
            bv + i * C_, nullptr, nullptr, nullptr, nullptr,
            nullptr, SCN, nullptr, nullptr, nullptr, 0, q, qT);

        // energy = qT @ q
        tgemm<EPI_PLAIN><<<gE, blk>>>(
            qT, SND, N_, D_, q, SDN, att, SNN,
            nullptr, nullptr, nullptr, nullptr, nullptr,
            nullptr, SCN, nullptr, nullptr, nullptr, 0, nullptr, nullptr);

        // row softmax
        softmax_kernel<<<B_ * N_, blk>>>(att);

        // d = rna(h - (val @ att) / colsum)
        tgemm<EPI_COLSCALE><<<gC, blk>>>(
            val, SCN, C_, N_, att, SNN, dbuf, SCN,
            nullptr, nullptr, nullptr, nullptr, nullptr,
            hcur, SCN, nullptr, nullptr, nullptr, 0, nullptr, nullptr);

        // h_new = h + relu(bn(Wt @ d + bt)); out slice; hp = rna(h_new + pos)
        tgemm<EPI_T_UPDATE><<<gC, blk>>>(
            w_t + (long)i * C_ * C_, 0, C_, C_, dbuf, SCN, hnxt, SCN,
            bt + i * C_, bng + i * C_, bnb + i * C_, bnm + i * C_, bnv + i * C_,
            hcur, SCN, pos, hp,
            out + (long)i * C_ * N_, (long)4 * C_ * N_, nullptr, nullptr);

        float* tmp = hcur; hcur = hnxt; hnxt = tmp;
    }
}